// round 3
// baseline (speedup 1.0000x reference)
#include <cuda_runtime.h>
#include <math.h>

#define NN 2048
#define KK 16
#define MM 64

// ---------------- device scratch (no allocations allowed) ----------------
__device__ double g_acc = 0.0;          // kD resets after reading -> replay-safe
__device__ float  g_Ma[KK * KK];
__device__ float  g_Mb[KK * KK];
__device__ float  g_dd[NN * KK];

// ---------------- packed f32x2 helpers (operands must be aligned reg pairs) ----
typedef unsigned long long u64;
union F4U { float4 f; u64 u[2]; float s[4]; };

__device__ __forceinline__ u64 pk2(float lo, float hi) {
    u64 r; asm("mov.b64 %0, {%1, %2};" : "=l"(r) : "f"(lo), "f"(hi)); return r;
}
__device__ __forceinline__ u64 fma2_(u64 a, u64 b, u64 c) {
    u64 d; asm("fma.rn.f32x2 %0, %1, %2, %3;" : "=l"(d) : "l"(a), "l"(b), "l"(c)); return d;
}
__device__ __forceinline__ u64 add2_(u64 a, u64 b) {
    u64 d; asm("add.rn.f32x2 %0, %1, %2;" : "=l"(d) : "l"(a), "l"(b)); return d;
}
__device__ __forceinline__ float hsum2(u64 v) {
    float lo, hi; asm("mov.b64 {%0, %1}, %2;" : "=f"(lo), "=f"(hi) : "l"(v)); return lo + hi;
}
__device__ __forceinline__ float ex2_(float x) {
    float r; asm("ex2.approx.f32 %0, %1;" : "=f"(r) : "f"(x)); return r;
}

// ---------------- helpers ----------------
__device__ __forceinline__ float digammaf_(float x) {
    float r = 0.f;
    #pragma unroll 1
    while (x < 7.f) { r -= 1.f / x; x += 1.f; }
    float inv  = 1.f / x;
    float inv2 = inv * inv;
    return r + logf(x) - 0.5f * inv
         - inv2 * (0.0833333333333f
                 - inv2 * (0.00833333333333f
                 - inv2 * 0.00396825396825f));
}

__device__ __forceinline__ void block_add(double v) {
    #pragma unroll
    for (int o = 16; o; o >>= 1) v += __shfl_down_sync(0xffffffffu, v, o);
    __shared__ double sred[8];
    int lane = threadIdx.x & 31, w = threadIdx.x >> 5;
    if (lane == 0) sred[w] = v;
    __syncthreads();
    if (w == 0) {
        int nw = (blockDim.x + 31) >> 5;
        double t = (lane < nw) ? sred[lane] : 0.0;
        #pragma unroll
        for (int o = 4; o; o >>= 1) t += __shfl_down_sync(0xffffffffu, t, o);
        if (lane == 0) atomicAdd(&g_acc, t);
    }
}

// ---------------- kernel AB: block 0 = beta terms; blocks 1..8 = node terms ----
__global__ void kAB(const float* __restrict__ alphas, const float* __restrict__ betas,
                    const float* __restrict__ ap_, const float* __restrict__ bp_,
                    const float* __restrict__ mu, const float* __restrict__ w,
                    const float* __restrict__ b, const float* __restrict__ c,
                    const float* __restrict__ attr) {
    int t = threadIdx.x;
    if (blockIdx.x == 0) {
        __shared__ float sSa[KK * KK], sSb[KK * KK];
        float a  = expf(alphas[t]);
        float be = expf(betas[t]);
        float ap = expf(ap_[t]);
        float bp = expf(bp_[t]);
        float dia = digammaf_(ap);
        float dib = digammaf_(bp);
        float dis = digammaf_(ap + bp);
        float Sa = dia - dis, Sb = dib - dis;
        sSa[t] = Sa; sSb[t] = Sb;
        __syncthreads();
        int k = t >> 4, l = t & 15;
        g_Ma[t] = sSa[t] + sSa[l * KK + k];
        g_Mb[t] = sSb[t] + sSb[l * KK + k];
        double acc = 0.0;
        if (k <= l) {
            acc += (double)((a - 1.f) * Sa + (be - 1.f) * Sb);
            float lb = lgammaf(ap) + lgammaf(bp) - lgammaf(ap + bp);
            acc += (double)(lb - (ap - 1.f) * dia - (bp - 1.f) * dib
                            + (ap + bp - 2.f) * dis);
        }
        block_add(acc);
    } else {
        int i = (blockIdx.x - 1) * 256 + t;
        float me[KK];
        float mu0 = 0.f;
        #pragma unroll
        for (int k = 0; k < KK; k++) { me[k] = expf(mu[i * KK + k]); mu0 += me[k]; }
        float dmu0 = digammaf_(mu0);
        float a = 0.f;
        #pragma unroll
        for (int k = 0; k < KK; k++) {
            float d = digammaf_(me[k]);
            g_dd[i * KK + k] = d - dmu0;
            a += lgammaf(me[k]) - (me[k] - 1.f) * d;
        }
        a += (mu0 - (float)KK) * dmu0 - lgammaf(mu0);
        float inv = 1.f / mu0;
        float mn[KK];
        #pragma unroll
        for (int k = 0; k < KK; k++) mn[k] = me[k] * inv;
        float pz = 0.f;
        for (int m = 0; m < MM; m++) {
            float s = 0.f;
            #pragma unroll
            for (int k = 0; k < KK; k++) s += mn[k] * w[k * MM + m];
            pz += attr[i * MM + m] * (s + b[m]);
        }
        float cz = 0.f;
        #pragma unroll
        for (int k = 0; k < KK; k++) cz += c[k] * mn[k];
        block_add((double)a + (double)pz + (double)cz);
    }
}

// ---------------- kernel C: heavy pass, direct global reads, no staging ------
__global__ void __launch_bounds__(256) kC(const float* __restrict__ q,
                                          const int* __restrict__ adj) {
    __shared__ float sM[520];            // Ma @0 (260 slots), Mb @260 (1040B apart)
    __shared__ float sddI[256], sddJ[256];

    int bid = blockIdx.x;
    int ti = (int)((sqrtf(8.f * (float)bid + 1.f) - 1.f) * 0.5f);
    while ((ti + 1) * (ti + 2) / 2 <= bid) ti++;
    while (ti * (ti + 1) / 2 > bid) ti--;
    int tj = bid - ti * (ti + 1) / 2;

    int t = threadIdx.x;
    sM[t < 256 ? t : 0] = g_Ma[t];       // (t always <256)
    sM[260 + t] = g_Mb[t];
    sddI[t] = g_dd[ti * 256 + t];        // 16 rows of dd, contiguous
    sddJ[t] = g_dd[tj * 256 + t];
    __syncthreads();

    int r = t >> 4, cc = t & 15;
    int i = ti * 16 + r, j = tj * 16 + cc;

    const float4* q4 = (const float4*)q;
    size_t bij = ((size_t)i * NN + j) * 4;   // q[i,j,:] as 4 float4
    size_t bji = ((size_t)j * NN + i) * 4;   // q[j,i,:] as 4 float4

    const float4* dI4 = (const float4*)(sddI + r * 16);
    const float4* dJ4 = (const float4*)(sddJ + cc * 16);

    const u64 zero2 = pk2(0.f, 0.f);
    const float L2E = 1.4426950408889634f;

    // ---- ij side: packed reductions; keep pe_ij packed for the bilinear ----
    u64 pe[8];
    u64 Z2 = zero2, dx2 = zero2, sd2 = zero2;
    #pragma unroll
    for (int p = 0; p < 4; p++) {
        F4U v; v.f = __ldg(&q4[bij + p]);
        float e0 = ex2_(v.s[0] * L2E), e1 = ex2_(v.s[1] * L2E);
        float e2 = ex2_(v.s[2] * L2E), e3 = ex2_(v.s[3] * L2E);
        u64 pa = pk2(e0, e1), pb = pk2(e2, e3);
        pe[2 * p] = pa; pe[2 * p + 1] = pb;
        Z2  = add2_(Z2, add2_(pa, pb));
        dx2 = fma2_(pa, v.u[0], dx2);
        dx2 = fma2_(pb, v.u[1], dx2);
        F4U d; d.f = dI4[p];
        sd2 = fma2_(pa, d.u[0], sd2);
        sd2 = fma2_(pb, d.u[1], sd2);
    }

    // ---- ji side: scalar reductions; keep e_ji scalar for the bilinear ----
    float eji[KK];
    float Zj = 0.f, dxj = 0.f, sdj = 0.f;
    #pragma unroll
    for (int p = 0; p < 4; p++) {
        F4U v; v.f = __ldg(&q4[bji + p]);
        F4U d; d.f = dJ4[p];
        #pragma unroll
        for (int u = 0; u < 4; u++) {
            float x = v.s[u];
            float e = ex2_(x * L2E);
            eji[p * 4 + u] = e;
            Zj  += e;
            dxj = fmaf(e, x, dxj);
            sdj = fmaf(e, d.s[u], sdj);
        }
    }

    // ---- bilinear: tsum = e_ji^T M e_ij, M = Ma(edge) / Mb(non-edge) ----
    int av = adj[(size_t)i * NN + j];
    const float* Mbase = sM + (av ? 0 : 260);
    float tsum = 0.f;
    #pragma unroll
    for (int k = 0; k < KK; k++) {
        F4U m0, m1;
        m0.f = *(const float4*)(Mbase + k * 16);
        m1.f = *(const float4*)(Mbase + k * 16 + 4);
        u64 r2 = fma2_(m0.u[0], pe[0], zero2);
        r2 = fma2_(m0.u[1], pe[1], r2);
        r2 = fma2_(m1.u[0], pe[2], r2);
        r2 = fma2_(m1.u[1], pe[3], r2);
        F4U m2, m3;
        m2.f = *(const float4*)(Mbase + k * 16 + 8);
        m3.f = *(const float4*)(Mbase + k * 16 + 12);
        r2 = fma2_(m2.u[0], pe[4], r2);
        r2 = fma2_(m2.u[1], pe[5], r2);
        r2 = fma2_(m3.u[0], pe[6], r2);
        r2 = fma2_(m3.u[1], pe[7], r2);
        tsum = fmaf(eji[k], hsum2(r2), tsum);
    }

    float Zi = hsum2(Z2);
    float dxi = hsum2(dx2);
    float sdi = hsum2(sd2);

    float rZi = __fdividef(1.f, Zi);
    float rZj = __fdividef(1.f, Zj);
    float contrib = sdi * rZi + sdj * rZj
                  - (dxi * rZi - __logf(Zi))
                  - (dxj * rZj - __logf(Zj))
                  + tsum * rZi * rZj;

    block_add((i > j) ? (double)contrib : 0.0);
}

// ---------------- kernel D: finalize + reset accumulator ----------------
__global__ void kD(float* out) {
    double v = g_acc;
    out[0] = (float)(-v);
    g_acc = 0.0;                        // ready for next graph replay
}

// ---------------- launch ----------------
extern "C" void kernel_launch(void* const* d_in, const int* in_sizes, int n_in,
                              void* d_out, int out_size) {
    const float* alphas = (const float*)d_in[0];
    const float* betas  = (const float*)d_in[1];
    const float* ap     = (const float*)d_in[2];
    const float* bp     = (const float*)d_in[3];
    const float* mu     = (const float*)d_in[4];
    const float* q      = (const float*)d_in[5];
    const float* w      = (const float*)d_in[6];
    const float* b      = (const float*)d_in[7];
    const float* c      = (const float*)d_in[8];
    const float* attr   = (const float*)d_in[9];
    const int*   adj    = (const int*)d_in[10];

    kAB<<<9, 256>>>(alphas, betas, ap, bp, mu, w, b, c, attr);
    kC<<<(128 * 129) / 2, 256>>>(q, adj);
    kD<<<1, 1>>>((float*)d_out);
}

// round 5
// speedup vs baseline: 1.0007x; 1.0007x over previous
#include <cuda_runtime.h>
#include <math.h>

#define NN 2048
#define KK 16
#define MM 64

// ---------------- device scratch (no allocations allowed) ----------------
__device__ double g_acc = 0.0;          // kD resets after reading -> replay-safe
__device__ float  g_Ma[KK * KK];
__device__ float  g_Mb[KK * KK];
__device__ float  g_dd[NN * KK];

// ---------------- packed f32x2 helpers (operands must be aligned reg pairs) ----
typedef unsigned long long u64;
union F4U { float4 f; u64 u[2]; float s[4]; };

__device__ __forceinline__ u64 pk2(float lo, float hi) {
    u64 r; asm("mov.b64 %0, {%1, %2};" : "=l"(r) : "f"(lo), "f"(hi)); return r;
}
__device__ __forceinline__ u64 fma2_(u64 a, u64 b, u64 c) {
    u64 d; asm("fma.rn.f32x2 %0, %1, %2, %3;" : "=l"(d) : "l"(a), "l"(b), "l"(c)); return d;
}
__device__ __forceinline__ u64 add2_(u64 a, u64 b) {
    u64 d; asm("add.rn.f32x2 %0, %1, %2;" : "=l"(d) : "l"(a), "l"(b)); return d;
}
__device__ __forceinline__ float hsum2(u64 v) {
    float lo, hi; asm("mov.b64 {%0, %1}, %2;" : "=f"(lo), "=f"(hi) : "l"(v)); return lo + hi;
}
__device__ __forceinline__ float ex2_(float x) {
    float r; asm("ex2.approx.f32 %0, %1;" : "=f"(r) : "f"(x)); return r;
}

// ---------------- helpers ----------------
__device__ __forceinline__ float digammaf_(float x) {
    float r = 0.f;
    #pragma unroll 1
    while (x < 7.f) { r -= 1.f / x; x += 1.f; }
    float inv  = 1.f / x;
    float inv2 = inv * inv;
    return r + logf(x) - 0.5f * inv
         - inv2 * (0.0833333333333f
                 - inv2 * (0.00833333333333f
                 - inv2 * 0.00396825396825f));
}

__device__ __forceinline__ void block_add(double v) {
    #pragma unroll
    for (int o = 16; o; o >>= 1) v += __shfl_down_sync(0xffffffffu, v, o);
    __shared__ double sred[8];
    int lane = threadIdx.x & 31, w = threadIdx.x >> 5;
    if (lane == 0) sred[w] = v;
    __syncthreads();
    if (w == 0) {
        int nw = (blockDim.x + 31) >> 5;
        double t = (lane < nw) ? sred[lane] : 0.0;
        #pragma unroll
        for (int o = 4; o; o >>= 1) t += __shfl_down_sync(0xffffffffu, t, o);
        if (lane == 0) atomicAdd(&g_acc, t);
    }
}

// ---------------- kernel AB: block 0 = beta terms; blocks 1..8 = node terms ----
__global__ void kAB(const float* __restrict__ alphas, const float* __restrict__ betas,
                    const float* __restrict__ ap_, const float* __restrict__ bp_,
                    const float* __restrict__ mu, const float* __restrict__ w,
                    const float* __restrict__ b, const float* __restrict__ c,
                    const float* __restrict__ attr) {
    int t = threadIdx.x;
    if (blockIdx.x == 0) {
        __shared__ float sSa[KK * KK], sSb[KK * KK];
        float a  = expf(alphas[t]);
        float be = expf(betas[t]);
        float ap = expf(ap_[t]);
        float bp = expf(bp_[t]);
        float dia = digammaf_(ap);
        float dib = digammaf_(bp);
        float dis = digammaf_(ap + bp);
        float Sa = dia - dis, Sb = dib - dis;
        sSa[t] = Sa; sSb[t] = Sb;
        __syncthreads();
        int k = t >> 4, l = t & 15;
        g_Ma[t] = sSa[t] + sSa[l * KK + k];
        g_Mb[t] = sSb[t] + sSb[l * KK + k];
        double acc = 0.0;
        if (k <= l) {
            acc += (double)((a - 1.f) * Sa + (be - 1.f) * Sb);
            float lb = lgammaf(ap) + lgammaf(bp) - lgammaf(ap + bp);
            acc += (double)(lb - (ap - 1.f) * dia - (bp - 1.f) * dib
                            + (ap + bp - 2.f) * dis);
        }
        block_add(acc);
    } else {
        int i = (blockIdx.x - 1) * 256 + t;
        float me[KK];
        float mu0 = 0.f;
        #pragma unroll
        for (int k = 0; k < KK; k++) { me[k] = expf(mu[i * KK + k]); mu0 += me[k]; }
        float dmu0 = digammaf_(mu0);
        float a = 0.f;
        #pragma unroll
        for (int k = 0; k < KK; k++) {
            float d = digammaf_(me[k]);
            g_dd[i * KK + k] = d - dmu0;
            a += lgammaf(me[k]) - (me[k] - 1.f) * d;
        }
        a += (mu0 - (float)KK) * dmu0 - lgammaf(mu0);
        float inv = 1.f / mu0;
        float mn[KK];
        #pragma unroll
        for (int k = 0; k < KK; k++) mn[k] = me[k] * inv;
        float pz = 0.f;
        for (int m = 0; m < MM; m++) {
            float s = 0.f;
            #pragma unroll
            for (int k = 0; k < KK; k++) s += mn[k] * w[k * MM + m];
            pz += attr[i * MM + m] * (s + b[m]);
        }
        float cz = 0.f;
        #pragma unroll
        for (int k = 0; k < KK; k++) cz += c[k] * mn[k];
        block_add((double)a + (double)pz + (double)cz);
    }
}

// ---------------- kernel C: heavy pass, direct global reads, no staging ------
__global__ void __launch_bounds__(256) kC(const float* __restrict__ q,
                                          const int* __restrict__ adj) {
    __shared__ float sM[520];            // Ma @0 (260 slots), Mb @260 (1040B apart)
    __shared__ float sddI[256], sddJ[256];

    int bid = blockIdx.x;
    int ti = (int)((sqrtf(8.f * (float)bid + 1.f) - 1.f) * 0.5f);
    while ((ti + 1) * (ti + 2) / 2 <= bid) ti++;
    while (ti * (ti + 1) / 2 > bid) ti--;
    int tj = bid - ti * (ti + 1) / 2;

    int t = threadIdx.x;
    sM[t < 256 ? t : 0] = g_Ma[t];       // (t always <256)
    sM[260 + t] = g_Mb[t];
    sddI[t] = g_dd[ti * 256 + t];        // 16 rows of dd, contiguous
    sddJ[t] = g_dd[tj * 256 + t];
    __syncthreads();

    int r = t >> 4, cc = t & 15;
    int i = ti * 16 + r, j = tj * 16 + cc;

    const float4* q4 = (const float4*)q;
    size_t bij = ((size_t)i * NN + j) * 4;   // q[i,j,:] as 4 float4
    size_t bji = ((size_t)j * NN + i) * 4;   // q[j,i,:] as 4 float4

    const float4* dI4 = (const float4*)(sddI + r * 16);
    const float4* dJ4 = (const float4*)(sddJ + cc * 16);

    const u64 zero2 = pk2(0.f, 0.f);
    const float L2E = 1.4426950408889634f;

    // ---- ij side: packed reductions; keep pe_ij packed for the bilinear ----
    u64 pe[8];
    u64 Z2 = zero2, dx2 = zero2, sd2 = zero2;
    #pragma unroll
    for (int p = 0; p < 4; p++) {
        F4U v; v.f = __ldg(&q4[bij + p]);
        float e0 = ex2_(v.s[0] * L2E), e1 = ex2_(v.s[1] * L2E);
        float e2 = ex2_(v.s[2] * L2E), e3 = ex2_(v.s[3] * L2E);
        u64 pa = pk2(e0, e1), pb = pk2(e2, e3);
        pe[2 * p] = pa; pe[2 * p + 1] = pb;
        Z2  = add2_(Z2, add2_(pa, pb));
        dx2 = fma2_(pa, v.u[0], dx2);
        dx2 = fma2_(pb, v.u[1], dx2);
        F4U d; d.f = dI4[p];
        sd2 = fma2_(pa, d.u[0], sd2);
        sd2 = fma2_(pb, d.u[1], sd2);
    }

    // ---- ji side: scalar reductions; keep e_ji scalar for the bilinear ----
    float eji[KK];
    float Zj = 0.f, dxj = 0.f, sdj = 0.f;
    #pragma unroll
    for (int p = 0; p < 4; p++) {
        F4U v; v.f = __ldg(&q4[bji + p]);
        F4U d; d.f = dJ4[p];
        #pragma unroll
        for (int u = 0; u < 4; u++) {
            float x = v.s[u];
            float e = ex2_(x * L2E);
            eji[p * 4 + u] = e;
            Zj  += e;
            dxj = fmaf(e, x, dxj);
            sdj = fmaf(e, d.s[u], sdj);
        }
    }

    // ---- bilinear: tsum = e_ji^T M e_ij, M = Ma(edge) / Mb(non-edge) ----
    int av = adj[(size_t)i * NN + j];
    const float* Mbase = sM + (av ? 0 : 260);
    float tsum = 0.f;
    #pragma unroll
    for (int k = 0; k < KK; k++) {
        F4U m0, m1;
        m0.f = *(const float4*)(Mbase + k * 16);
        m1.f = *(const float4*)(Mbase + k * 16 + 4);
        u64 r2 = fma2_(m0.u[0], pe[0], zero2);
        r2 = fma2_(m0.u[1], pe[1], r2);
        r2 = fma2_(m1.u[0], pe[2], r2);
        r2 = fma2_(m1.u[1], pe[3], r2);
        F4U m2, m3;
        m2.f = *(const float4*)(Mbase + k * 16 + 8);
        m3.f = *(const float4*)(Mbase + k * 16 + 12);
        r2 = fma2_(m2.u[0], pe[4], r2);
        r2 = fma2_(m2.u[1], pe[5], r2);
        r2 = fma2_(m3.u[0], pe[6], r2);
        r2 = fma2_(m3.u[1], pe[7], r2);
        tsum = fmaf(eji[k], hsum2(r2), tsum);
    }

    float Zi = hsum2(Z2);
    float dxi = hsum2(dx2);
    float sdi = hsum2(sd2);

    float rZi = __fdividef(1.f, Zi);
    float rZj = __fdividef(1.f, Zj);
    float contrib = sdi * rZi + sdj * rZj
                  - (dxi * rZi - __logf(Zi))
                  - (dxj * rZj - __logf(Zj))
                  + tsum * rZi * rZj;

    block_add((i > j) ? (double)contrib : 0.0);
}

// ---------------- kernel D: finalize + reset accumulator ----------------
__global__ void kD(float* out) {
    double v = g_acc;
    out[0] = (float)(-v);
    g_acc = 0.0;                        // ready for next graph replay
}

// ---------------- launch ----------------
extern "C" void kernel_launch(void* const* d_in, const int* in_sizes, int n_in,
                              void* d_out, int out_size) {
    const float* alphas = (const float*)d_in[0];
    const float* betas  = (const float*)d_in[1];
    const float* ap     = (const float*)d_in[2];
    const float* bp     = (const float*)d_in[3];
    const float* mu     = (const float*)d_in[4];
    const float* q      = (const float*)d_in[5];
    const float* w      = (const float*)d_in[6];
    const float* b      = (const float*)d_in[7];
    const float* c      = (const float*)d_in[8];
    const float* attr   = (const float*)d_in[9];
    const int*   adj    = (const int*)d_in[10];

    kAB<<<9, 256>>>(alphas, betas, ap, bp, mu, w, b, c, attr);
    kC<<<(128 * 129) / 2, 256>>>(q, adj);
    kD<<<1, 1>>>((float*)d_out);
}